// round 1
// baseline (speedup 1.0000x reference)
#include <cuda_runtime.h>
#include <cuda_bf16.h>
#include <math.h>

#define NN 100000
#define EE 6400000
#define IN_CH 128

// ---------------- scratch (static device memory; no allocations) -------------
__device__ __align__(16) float g_h1[NN * 10];     // layer1 features [N,2,5]
__device__ __align__(16) float g_as1[NN * 2];     // alpha_src layer1 (float2/node)
__device__ __align__(16) float g_ad1[NN * 2];     // alpha_dst layer1
__device__ __align__(16) float g_rec1[NN * 12];   // [d0,d1,n00..n04,n10..n14]
__device__ __align__(16) float g_t1[NN * 10];     // post-aggregation layer1 (pre-BN)
__device__ double g_bnsum[10];
__device__ double g_bnsumsq[10];
__device__ float g_scale[10];
__device__ float g_shift[10];
__device__ __align__(16) float g_h2[NN * 10];     // layer2 features [N,10]
__device__ float g_as2[NN];
__device__ float g_ad2[NN];
__device__ __align__(16) float g_rec2[NN * 12];   // [den,n0..n9,pad]
__device__ int g_src[EE];
__device__ int g_dst[EE];
__device__ int g_is64;

// vector fp32 reduction to global (sm_90+)
__device__ __forceinline__ void red4(float* p, float a, float b, float c, float d) {
    asm volatile("red.global.add.v4.f32 [%0], {%1,%2,%3,%4};"
                 :: "l"(p), "f"(a), "f"(b), "f"(c), "f"(d) : "memory");
}

__device__ __forceinline__ float lrelu(float v) { return v > 0.f ? v : 0.2f * v; }

// ---------------- K0a: detect edge_index dtype (int64 vs int32) -------------
__global__ void k_detect(const long long* __restrict__ ei) {
    if (threadIdx.x == 0) {
        int ok = 1;
        for (int i = 0; i < 64; i++) {
            long long v = ei[i];
            if (v < 0 || v >= NN) ok = 0;
        }
        g_is64 = ok;  // all plausible as int64 -> data is int64
    }
}

// ---------------- K0b: narrow edge_index to int32 src/dst arrays ------------
__global__ void k_convert(const void* __restrict__ ei) {
    int i = blockIdx.x * blockDim.x + threadIdx.x;
    if (i >= EE) return;
    if (g_is64) {
        const long long* p = (const long long*)ei;
        g_src[i] = (int)p[i];
        g_dst[i] = (int)p[EE + i];
    } else {
        const int* p = (const int*)ei;
        g_src[i] = p[i];
        g_dst[i] = p[EE + i];
    }
}

// ---------------- K1: layer1 node kernel (one warp per node) ----------------
// h1 = x @ W1; alpha_src/dst; init accumulators with self-loop contribution.
__global__ void k1(const float* __restrict__ x, const float* __restrict__ W1,
                   const float* __restrict__ a1s, const float* __restrict__ a1d) {
    if (blockIdx.x == 0 && threadIdx.x < 10) {
        g_bnsum[threadIdx.x] = 0.0;
        g_bnsumsq[threadIdx.x] = 0.0;
    }
    int lane = threadIdx.x & 31;
    int node = (blockIdx.x * blockDim.x + threadIdx.x) >> 5;
    if (node >= NN) return;

    // each lane owns 4 input channels
    float w[4][10];
#pragma unroll
    for (int kk = 0; kk < 4; kk++)
#pragma unroll
        for (int j = 0; j < 10; j++)
            w[kk][j] = __ldg(&W1[(lane * 4 + kk) * 10 + j]);

    float4 xv = *(const float4*)(x + (size_t)node * IN_CH + lane * 4);
    float acc[10];
#pragma unroll
    for (int j = 0; j < 10; j++)
        acc[j] = xv.x * w[0][j] + xv.y * w[1][j] + xv.z * w[2][j] + xv.w * w[3][j];
#pragma unroll
    for (int j = 0; j < 10; j++)
#pragma unroll
        for (int o = 16; o; o >>= 1)
            acc[j] += __shfl_xor_sync(0xffffffffu, acc[j], o);

    if (lane == 0) {
        float as0 = 0.f, as1v = 0.f, ad0 = 0.f, ad1v = 0.f;
#pragma unroll
        for (int c = 0; c < 5; c++) {
            as0  += acc[c]     * a1s[c];
            as1v += acc[5 + c] * a1s[5 + c];
            ad0  += acc[c]     * a1d[c];
            ad1v += acc[5 + c] * a1d[5 + c];
        }
        ((float2*)g_as1)[node] = make_float2(as0, as1v);
        ((float2*)g_ad1)[node] = make_float2(ad0, ad1v);
        float2* hp = (float2*)(g_h1 + (size_t)node * 10);
#pragma unroll
        for (int c = 0; c < 5; c++)
            hp[c] = make_float2(acc[2 * c], acc[2 * c + 1]);

        float x0 = __expf(lrelu(as0 + ad0));
        float x1 = __expf(lrelu(as1v + ad1v));
        float4* rec = (float4*)(g_rec1 + (size_t)node * 12);
        rec[0] = make_float4(x0, x1, x0 * acc[0], x0 * acc[1]);
        rec[1] = make_float4(x0 * acc[2], x0 * acc[3], x0 * acc[4], x1 * acc[5]);
        rec[2] = make_float4(x1 * acc[6], x1 * acc[7], x1 * acc[8], x1 * acc[9]);
    }
}

// ---------------- K2: layer1 edge kernel ------------------------------------
__global__ void k2() {
    int i = blockIdx.x * blockDim.x + threadIdx.x;
    if (i >= EE) return;
    int s = g_src[i];
    int d = g_dst[i];
    float2 as = ((const float2*)g_as1)[s];
    float2 ad = ((const float2*)g_ad1)[d];
    float x0 = __expf(lrelu(as.x + ad.x));
    float x1 = __expf(lrelu(as.y + ad.y));
    const float2* h = (const float2*)(g_h1 + (size_t)s * 10);
    float2 h01 = h[0], h23 = h[1], h45 = h[2], h67 = h[3], h89 = h[4];
    float* rec = g_rec1 + (size_t)d * 12;
    red4(rec,     x0,         x1,         x0 * h01.x, x0 * h01.y);
    red4(rec + 4, x0 * h23.x, x0 * h23.y, x0 * h45.x, x1 * h45.y);
    red4(rec + 8, x1 * h67.x, x1 * h67.y, x1 * h89.x, x1 * h89.y);
}

// ---------------- K3: finalize layer1 aggregation + BN stats ----------------
__global__ void k3(const float* __restrict__ b1) {
    __shared__ double ssum[10], ssq[10];
    if (threadIdx.x < 10) { ssum[threadIdx.x] = 0.0; ssq[threadIdx.x] = 0.0; }
    __syncthreads();
    int node = blockIdx.x * blockDim.x + threadIdx.x;
    int lane = threadIdx.x & 31;
    float t[10];
    if (node < NN) {
        const float4* rp = (const float4*)(g_rec1 + (size_t)node * 12);
        float4 r0 = rp[0], r1 = rp[1], r2 = rp[2];
        float i0 = 1.f / (r0.x + 1e-16f);
        float i1 = 1.f / (r0.y + 1e-16f);
        t[0] = r0.z * i0 + b1[0];
        t[1] = r0.w * i0 + b1[1];
        t[2] = r1.x * i0 + b1[2];
        t[3] = r1.y * i0 + b1[3];
        t[4] = r1.z * i0 + b1[4];
        t[5] = r1.w * i1 + b1[5];
        t[6] = r2.x * i1 + b1[6];
        t[7] = r2.y * i1 + b1[7];
        t[8] = r2.z * i1 + b1[8];
        t[9] = r2.w * i1 + b1[9];
        float2* tp = (float2*)(g_t1 + (size_t)node * 10);
#pragma unroll
        for (int c = 0; c < 5; c++)
            tp[c] = make_float2(t[2 * c], t[2 * c + 1]);
    } else {
#pragma unroll
        for (int j = 0; j < 10; j++) t[j] = 0.f;
    }
    // warp-reduce sums & sumsq, accumulate to shared (double), then global
#pragma unroll
    for (int j = 0; j < 10; j++) {
        float v = t[j];
        float s = t[j] * t[j];
#pragma unroll
        for (int o = 16; o; o >>= 1) {
            v += __shfl_xor_sync(0xffffffffu, v, o);
            s += __shfl_xor_sync(0xffffffffu, s, o);
        }
        if (lane == 0) {
            atomicAdd(&ssum[j], (double)v);
            atomicAdd(&ssq[j], (double)s);
        }
    }
    __syncthreads();
    if (threadIdx.x < 10) {
        atomicAdd(&g_bnsum[threadIdx.x], ssum[threadIdx.x]);
        atomicAdd(&g_bnsumsq[threadIdx.x], ssq[threadIdx.x]);
    }
}

// ---------------- K4: BN affine constants -----------------------------------
__global__ void k4(const float* __restrict__ gamma, const float* __restrict__ beta) {
    int j = threadIdx.x;
    if (j < 10) {
        double mean = g_bnsum[j] / (double)NN;
        double var = g_bnsumsq[j] / (double)NN - mean * mean;
        float sc = gamma[j] * (float)rsqrt(var + 1e-5);
        g_scale[j] = sc;
        g_shift[j] = beta[j] - (float)mean * sc;
    }
}

// ---------------- K5: BN apply + ELU + layer2 node kernel -------------------
__global__ void k5(const float* __restrict__ W2, const float* __restrict__ a2s,
                   const float* __restrict__ a2d) {
    __shared__ float sW[100], sa[10], sd[10], ssc[10], ssh[10];
    if (threadIdx.x < 100) sW[threadIdx.x] = W2[threadIdx.x];
    if (threadIdx.x < 10) {
        sa[threadIdx.x] = a2s[threadIdx.x];
        sd[threadIdx.x] = a2d[threadIdx.x];
        ssc[threadIdx.x] = g_scale[threadIdx.x];
        ssh[threadIdx.x] = g_shift[threadIdx.x];
    }
    __syncthreads();
    int node = blockIdx.x * blockDim.x + threadIdx.x;
    if (node >= NN) return;

    float y[10];
    const float2* tp = (const float2*)(g_t1 + (size_t)node * 10);
#pragma unroll
    for (int c = 0; c < 5; c++) {
        float2 v = tp[c];
        float u0 = v.x * ssc[2 * c] + ssh[2 * c];
        float u1 = v.y * ssc[2 * c + 1] + ssh[2 * c + 1];
        y[2 * c]     = u0 > 0.f ? u0 : expm1f(u0);
        y[2 * c + 1] = u1 > 0.f ? u1 : expm1f(u1);
    }
    float h[10];
#pragma unroll
    for (int c = 0; c < 10; c++) {
        float s = 0.f;
#pragma unroll
        for (int j = 0; j < 10; j++) s += y[j] * sW[j * 10 + c];
        h[c] = s;
    }
    float as = 0.f, ad = 0.f;
#pragma unroll
    for (int c = 0; c < 10; c++) {
        as += h[c] * sa[c];
        ad += h[c] * sd[c];
    }
    g_as2[node] = as;
    g_ad2[node] = ad;
    float2* hp = (float2*)(g_h2 + (size_t)node * 10);
#pragma unroll
    for (int c = 0; c < 5; c++)
        hp[c] = make_float2(h[2 * c], h[2 * c + 1]);

    float ex = __expf(lrelu(as + ad));  // self-loop
    float4* rec = (float4*)(g_rec2 + (size_t)node * 12);
    rec[0] = make_float4(ex, ex * h[0], ex * h[1], ex * h[2]);
    rec[1] = make_float4(ex * h[3], ex * h[4], ex * h[5], ex * h[6]);
    rec[2] = make_float4(ex * h[7], ex * h[8], ex * h[9], 0.f);
}

// ---------------- K6: layer2 edge kernel ------------------------------------
__global__ void k6() {
    int i = blockIdx.x * blockDim.x + threadIdx.x;
    if (i >= EE) return;
    int s = g_src[i];
    int d = g_dst[i];
    float ex = __expf(lrelu(g_as2[s] + g_ad2[d]));
    const float2* h = (const float2*)(g_h2 + (size_t)s * 10);
    float2 h01 = h[0], h23 = h[1], h45 = h[2], h67 = h[3], h89 = h[4];
    float* rec = g_rec2 + (size_t)d * 12;
    red4(rec,     ex,         ex * h01.x, ex * h01.y, ex * h23.x);
    red4(rec + 4, ex * h23.y, ex * h45.x, ex * h45.y, ex * h67.x);
    red4(rec + 8, ex * h67.y, ex * h89.x, ex * h89.y, 0.f);
}

// ---------------- K7: finalize output ---------------------------------------
__global__ void k7(float* __restrict__ out, const float* __restrict__ b2) {
    int idx = blockIdx.x * blockDim.x + threadIdx.x;
    if (idx >= NN * 10) return;
    int node = idx / 10;
    int c = idx - node * 10;
    const float* rec = g_rec2 + (size_t)node * 12;
    out[idx] = rec[1 + c] / (rec[0] + 1e-16f) + b2[c];
}

// ---------------- launch -----------------------------------------------------
extern "C" void kernel_launch(void* const* d_in, const int* in_sizes, int n_in,
                              void* d_out, int out_size) {
    (void)in_sizes; (void)n_in; (void)out_size;
    const float* x      = (const float*)d_in[0];
    const float* W1     = (const float*)d_in[1];
    const float* a_src1 = (const float*)d_in[2];
    const float* a_dst1 = (const float*)d_in[3];
    const float* b1     = (const float*)d_in[4];
    const float* gamma1 = (const float*)d_in[5];
    const float* beta1  = (const float*)d_in[6];
    const float* W2     = (const float*)d_in[7];
    const float* a_src2 = (const float*)d_in[8];
    const float* a_dst2 = (const float*)d_in[9];
    const float* b2     = (const float*)d_in[10];
    const void*  ei     = d_in[11];

    k_detect<<<1, 32>>>((const long long*)ei);
    k_convert<<<(EE + 255) / 256, 256>>>(ei);
    k1<<<(NN * 32 + 255) / 256, 256>>>(x, W1, a_src1, a_dst1);
    k2<<<(EE + 255) / 256, 256>>>();
    k3<<<(NN + 255) / 256, 256>>>(b1);
    k4<<<1, 32>>>(gamma1, beta1);
    k5<<<(NN + 255) / 256, 256>>>(W2, a_src2, a_dst2);
    k6<<<(EE + 255) / 256, 256>>>();
    k7<<<(NN * 10 + 255) / 256, 256>>>((float*)d_out, b2);
}

// round 2
// speedup vs baseline: 1.1721x; 1.1721x over previous
#include <cuda_runtime.h>
#include <cuda_bf16.h>
#include <math.h>

#define NN 100000
#define EE 6400000
#define IN_CH 128
#define TILE 512
#define NB ((NN + TILE - 1) / TILE)   // 196

// ---------------- scratch (static device memory) -----------------------------
__device__ __align__(16) float g_rec1[NN * 12];   // {as0,as1,h0..h9} per node
__device__ __align__(16) float g_ad1[NN * 2];     // alpha_dst layer1 (float2)
__device__ __align__(16) float g_t1[NN * 10];     // post-agg layer1 (pre-BN)
__device__ __align__(16) float g_rec2[NN * 12];   // {as2,h0..h9,pad} per node
__device__ float g_ad2[NN];
__device__ double g_bnsum[10];
__device__ double g_bnsumsq[10];
__device__ float g_scale[10];
__device__ float g_shift[10];
__device__ int g_deg[NN];
__device__ int g_rowstart[NN + 1];
__device__ int g_cur[NN];
__device__ int g_ssrc[EE];      // src ids sorted by dst
__device__ int g_partial[NB];
__device__ int g_tileoff[NB];
__device__ int g_is64;

__device__ __forceinline__ float lrelu(float v) { return v > 0.f ? v : 0.2f * v; }

// ---------------- K0: detect edge_index dtype --------------------------------
__global__ void k_detect(const long long* __restrict__ ei) {
    if (threadIdx.x == 0) {
        int ok = 1;
        for (int i = 0; i < 64; i++) {
            long long v = ei[i];
            if (v < 0 || v >= NN) ok = 0;
        }
        g_is64 = ok;
    }
}

// ---------------- KZ: zero deg + BN accumulators ------------------------------
__global__ void kz() {
    int i = blockIdx.x * blockDim.x + threadIdx.x;
    if (i < NN) g_deg[i] = 0;
    if (i < 10) { g_bnsum[i] = 0.0; g_bnsumsq[i] = 0.0; }
}

// ---------------- KH: histogram of dst ---------------------------------------
__global__ void khist(const void* __restrict__ ei) {
    int i = blockIdx.x * blockDim.x + threadIdx.x;
    if (i >= EE) return;
    int d;
    if (g_is64) d = (int)((const long long*)ei)[EE + i];
    else        d = ((const int*)ei)[EE + i];
    atomicAdd(&g_deg[d], 1);
}

// ---------------- scan (3 kernels) -------------------------------------------
__global__ void kscan1() {
    __shared__ int s[TILE];
    int b = blockIdx.x, t = threadIdx.x;
    int i = b * TILE + t;
    int v = (i < NN) ? g_deg[i] : 0;
    s[t] = v;
    __syncthreads();
#pragma unroll
    for (int o = 1; o < TILE; o <<= 1) {
        int u = (t >= o) ? s[t - o] : 0;
        __syncthreads();
        s[t] += u;
        __syncthreads();
    }
    if (i < NN) g_rowstart[i] = s[t] - v;   // local exclusive
    if (t == TILE - 1) g_partial[b] = s[t];
}

__global__ void kscan2() {
    __shared__ int s[256];
    int t = threadIdx.x;
    int v = (t < NB) ? g_partial[t] : 0;
    s[t] = v;
    __syncthreads();
#pragma unroll
    for (int o = 1; o < 256; o <<= 1) {
        int u = (t >= o) ? s[t - o] : 0;
        __syncthreads();
        s[t] += u;
        __syncthreads();
    }
    if (t < NB) g_tileoff[t] = s[t] - v;
}

__global__ void kscan3() {
    int i = blockIdx.x * blockDim.x + threadIdx.x;
    if (i < NN) {
        int rs = g_rowstart[i] + g_tileoff[i / TILE];
        g_rowstart[i] = rs;
        g_cur[i] = rs;
    }
    if (i == 0) g_rowstart[NN] = EE;
}

// ---------------- KS: scatter src into dst-sorted order ----------------------
__global__ void kscatter(const void* __restrict__ ei) {
    int i = blockIdx.x * blockDim.x + threadIdx.x;
    if (i >= EE) return;
    int s, d;
    if (g_is64) {
        const long long* p = (const long long*)ei;
        s = (int)p[i];
        d = (int)p[EE + i];
    } else {
        const int* p = (const int*)ei;
        s = p[i];
        d = p[EE + i];
    }
    int pos = atomicAdd(&g_cur[d], 1);
    g_ssrc[pos] = s;
}

// ---------------- K1: layer1 node GEMM (warp per node) -----------------------
__global__ void k1(const float* __restrict__ x, const float* __restrict__ W1,
                   const float* __restrict__ a1s, const float* __restrict__ a1d) {
    int lane = threadIdx.x & 31;
    int node = (blockIdx.x * blockDim.x + threadIdx.x) >> 5;
    if (node >= NN) return;

    float w[4][10];
#pragma unroll
    for (int kk = 0; kk < 4; kk++)
#pragma unroll
        for (int j = 0; j < 10; j++)
            w[kk][j] = __ldg(&W1[(lane * 4 + kk) * 10 + j]);

    float4 xv = *(const float4*)(x + (size_t)node * IN_CH + lane * 4);
    float acc[10];
#pragma unroll
    for (int j = 0; j < 10; j++)
        acc[j] = xv.x * w[0][j] + xv.y * w[1][j] + xv.z * w[2][j] + xv.w * w[3][j];
#pragma unroll
    for (int j = 0; j < 10; j++)
#pragma unroll
        for (int o = 16; o; o >>= 1)
            acc[j] += __shfl_xor_sync(0xffffffffu, acc[j], o);

    if (lane == 0) {
        float as0 = 0.f, as1v = 0.f, ad0 = 0.f, ad1v = 0.f;
#pragma unroll
        for (int c = 0; c < 5; c++) {
            as0  += acc[c]     * a1s[c];
            as1v += acc[5 + c] * a1s[5 + c];
            ad0  += acc[c]     * a1d[c];
            ad1v += acc[5 + c] * a1d[5 + c];
        }
        ((float2*)g_ad1)[node] = make_float2(ad0, ad1v);
        float4* rec = (float4*)(g_rec1 + (size_t)node * 12);
        rec[0] = make_float4(as0, as1v, acc[0], acc[1]);
        rec[1] = make_float4(acc[2], acc[3], acc[4], acc[5]);
        rec[2] = make_float4(acc[6], acc[7], acc[8], acc[9]);
    }
}

// ---------------- KE1: layer1 edge aggregation (warp per dst node) -----------
__global__ void kedge1(const float* __restrict__ b1) {
    int lane = threadIdx.x & 31;
    int d = (blockIdx.x * blockDim.x + threadIdx.x) >> 5;
    if (d >= NN) return;
    int rs = g_rowstart[d];
    int re = g_rowstart[d + 1];
    float2 ad = ((const float2*)g_ad1)[d];

    float acc[12];
#pragma unroll
    for (int j = 0; j < 12; j++) acc[j] = 0.f;

    if (lane == 0) {  // self loop
        const float4* rp = (const float4*)(g_rec1 + (size_t)d * 12);
        float4 r0 = rp[0], r1 = rp[1], r2 = rp[2];
        float x0 = __expf(lrelu(r0.x + ad.x));
        float x1 = __expf(lrelu(r0.y + ad.y));
        acc[0] = x0; acc[1] = x1;
        acc[2] = x0 * r0.z; acc[3] = x0 * r0.w;
        acc[4] = x0 * r1.x; acc[5] = x0 * r1.y; acc[6] = x0 * r1.z;
        acc[7] = x1 * r1.w; acc[8] = x1 * r2.x; acc[9] = x1 * r2.y;
        acc[10] = x1 * r2.z; acc[11] = x1 * r2.w;
    }
    for (int j = rs + lane; j < re; j += 32) {
        int s = g_ssrc[j];
        const float4* rp = (const float4*)(g_rec1 + (size_t)s * 12);
        float4 r0 = rp[0], r1 = rp[1], r2 = rp[2];
        float x0 = __expf(lrelu(r0.x + ad.x));
        float x1 = __expf(lrelu(r0.y + ad.y));
        acc[0] += x0; acc[1] += x1;
        acc[2] += x0 * r0.z; acc[3] += x0 * r0.w;
        acc[4] += x0 * r1.x; acc[5] += x0 * r1.y; acc[6] += x0 * r1.z;
        acc[7] += x1 * r1.w; acc[8] += x1 * r2.x; acc[9] += x1 * r2.y;
        acc[10] += x1 * r2.z; acc[11] += x1 * r2.w;
    }
#pragma unroll
    for (int j = 0; j < 12; j++)
#pragma unroll
        for (int o = 16; o; o >>= 1)
            acc[j] += __shfl_xor_sync(0xffffffffu, acc[j], o);

    if (lane == 0) {
        float i0 = 1.f / (acc[0] + 1e-16f);
        float i1 = 1.f / (acc[1] + 1e-16f);
        float2* tp = (float2*)(g_t1 + (size_t)d * 10);
        tp[0] = make_float2(acc[2] * i0 + b1[0], acc[3] * i0 + b1[1]);
        tp[1] = make_float2(acc[4] * i0 + b1[2], acc[5] * i0 + b1[3]);
        tp[2] = make_float2(acc[6] * i0 + b1[4], acc[7] * i1 + b1[5]);
        tp[3] = make_float2(acc[8] * i1 + b1[6], acc[9] * i1 + b1[7]);
        tp[4] = make_float2(acc[10] * i1 + b1[8], acc[11] * i1 + b1[9]);
    }
}

// ---------------- KBN: BN statistics -----------------------------------------
__global__ void kbn() {
    __shared__ double ssum[10], ssq[10];
    if (threadIdx.x < 10) { ssum[threadIdx.x] = 0.0; ssq[threadIdx.x] = 0.0; }
    __syncthreads();
    int node = blockIdx.x * blockDim.x + threadIdx.x;
    int lane = threadIdx.x & 31;
    float t[10];
    if (node < NN) {
        const float2* tp = (const float2*)(g_t1 + (size_t)node * 10);
#pragma unroll
        for (int c = 0; c < 5; c++) {
            float2 v = tp[c];
            t[2 * c] = v.x;
            t[2 * c + 1] = v.y;
        }
    } else {
#pragma unroll
        for (int j = 0; j < 10; j++) t[j] = 0.f;
    }
#pragma unroll
    for (int j = 0; j < 10; j++) {
        float v = t[j];
        float s = t[j] * t[j];
#pragma unroll
        for (int o = 16; o; o >>= 1) {
            v += __shfl_xor_sync(0xffffffffu, v, o);
            s += __shfl_xor_sync(0xffffffffu, s, o);
        }
        if (lane == 0) {
            atomicAdd(&ssum[j], (double)v);
            atomicAdd(&ssq[j], (double)s);
        }
    }
    __syncthreads();
    if (threadIdx.x < 10) {
        atomicAdd(&g_bnsum[threadIdx.x], ssum[threadIdx.x]);
        atomicAdd(&g_bnsumsq[threadIdx.x], ssq[threadIdx.x]);
    }
}

// ---------------- K4: BN affine constants ------------------------------------
__global__ void k4(const float* __restrict__ gamma, const float* __restrict__ beta) {
    int j = threadIdx.x;
    if (j < 10) {
        double mean = g_bnsum[j] / (double)NN;
        double var = g_bnsumsq[j] / (double)NN - mean * mean;
        float sc = gamma[j] * (float)rsqrt(var + 1e-5);
        g_scale[j] = sc;
        g_shift[j] = beta[j] - (float)mean * sc;
    }
}

// ---------------- K5: BN + ELU + layer2 node GEMM ----------------------------
__global__ void k5(const float* __restrict__ W2, const float* __restrict__ a2s,
                   const float* __restrict__ a2d) {
    __shared__ float sW[100], sa[10], sd[10], ssc[10], ssh[10];
    if (threadIdx.x < 100) sW[threadIdx.x] = W2[threadIdx.x];
    if (threadIdx.x < 10) {
        sa[threadIdx.x] = a2s[threadIdx.x];
        sd[threadIdx.x] = a2d[threadIdx.x];
        ssc[threadIdx.x] = g_scale[threadIdx.x];
        ssh[threadIdx.x] = g_shift[threadIdx.x];
    }
    __syncthreads();
    int node = blockIdx.x * blockDim.x + threadIdx.x;
    if (node >= NN) return;

    float y[10];
    const float2* tp = (const float2*)(g_t1 + (size_t)node * 10);
#pragma unroll
    for (int c = 0; c < 5; c++) {
        float2 v = tp[c];
        float u0 = v.x * ssc[2 * c] + ssh[2 * c];
        float u1 = v.y * ssc[2 * c + 1] + ssh[2 * c + 1];
        y[2 * c]     = u0 > 0.f ? u0 : expm1f(u0);
        y[2 * c + 1] = u1 > 0.f ? u1 : expm1f(u1);
    }
    float h[10];
#pragma unroll
    for (int c = 0; c < 10; c++) {
        float s = 0.f;
#pragma unroll
        for (int j = 0; j < 10; j++) s += y[j] * sW[j * 10 + c];
        h[c] = s;
    }
    float as = 0.f, ad = 0.f;
#pragma unroll
    for (int c = 0; c < 10; c++) {
        as += h[c] * sa[c];
        ad += h[c] * sd[c];
    }
    g_ad2[node] = ad;
    float4* rec = (float4*)(g_rec2 + (size_t)node * 12);
    rec[0] = make_float4(as, h[0], h[1], h[2]);
    rec[1] = make_float4(h[3], h[4], h[5], h[6]);
    rec[2] = make_float4(h[7], h[8], h[9], 0.f);
}

// ---------------- KE2: layer2 edge aggregation -> output ---------------------
__global__ void kedge2(float* __restrict__ out, const float* __restrict__ b2) {
    int lane = threadIdx.x & 31;
    int d = (blockIdx.x * blockDim.x + threadIdx.x) >> 5;
    if (d >= NN) return;
    int rs = g_rowstart[d];
    int re = g_rowstart[d + 1];
    float ad = g_ad2[d];

    float acc[11];
#pragma unroll
    for (int j = 0; j < 11; j++) acc[j] = 0.f;

    if (lane == 0) {  // self loop
        const float4* rp = (const float4*)(g_rec2 + (size_t)d * 12);
        float4 r0 = rp[0], r1 = rp[1], r2 = rp[2];
        float ex = __expf(lrelu(r0.x + ad));
        acc[0] = ex;
        acc[1] = ex * r0.y; acc[2] = ex * r0.z; acc[3] = ex * r0.w;
        acc[4] = ex * r1.x; acc[5] = ex * r1.y; acc[6] = ex * r1.z;
        acc[7] = ex * r1.w; acc[8] = ex * r2.x; acc[9] = ex * r2.y;
        acc[10] = ex * r2.z;
    }
    for (int j = rs + lane; j < re; j += 32) {
        int s = g_ssrc[j];
        const float4* rp = (const float4*)(g_rec2 + (size_t)s * 12);
        float4 r0 = rp[0], r1 = rp[1], r2 = rp[2];
        float ex = __expf(lrelu(r0.x + ad));
        acc[0] += ex;
        acc[1] += ex * r0.y; acc[2] += ex * r0.z; acc[3] += ex * r0.w;
        acc[4] += ex * r1.x; acc[5] += ex * r1.y; acc[6] += ex * r1.z;
        acc[7] += ex * r1.w; acc[8] += ex * r2.x; acc[9] += ex * r2.y;
        acc[10] += ex * r2.z;
    }
#pragma unroll
    for (int j = 0; j < 11; j++)
#pragma unroll
        for (int o = 16; o; o >>= 1)
            acc[j] += __shfl_xor_sync(0xffffffffu, acc[j], o);

    if (lane == 0) {
        float inv = 1.f / (acc[0] + 1e-16f);
        float* op = out + (size_t)d * 10;
#pragma unroll
        for (int c = 0; c < 10; c++)
            op[c] = acc[1 + c] * inv + b2[c];
    }
}

// ---------------- launch ------------------------------------------------------
extern "C" void kernel_launch(void* const* d_in, const int* in_sizes, int n_in,
                              void* d_out, int out_size) {
    (void)in_sizes; (void)n_in; (void)out_size;
    const float* x      = (const float*)d_in[0];
    const float* W1     = (const float*)d_in[1];
    const float* a_src1 = (const float*)d_in[2];
    const float* a_dst1 = (const float*)d_in[3];
    const float* b1     = (const float*)d_in[4];
    const float* gamma1 = (const float*)d_in[5];
    const float* beta1  = (const float*)d_in[6];
    const float* W2     = (const float*)d_in[7];
    const float* a_src2 = (const float*)d_in[8];
    const float* a_dst2 = (const float*)d_in[9];
    const float* b2     = (const float*)d_in[10];
    const void*  ei     = d_in[11];

    k_detect<<<1, 32>>>((const long long*)ei);
    kz<<<(NN + 255) / 256, 256>>>();
    khist<<<(EE + 255) / 256, 256>>>(ei);
    kscan1<<<NB, TILE>>>();
    kscan2<<<1, 256>>>();
    kscan3<<<(NN + 255) / 256, 256>>>();
    kscatter<<<(EE + 255) / 256, 256>>>(ei);
    k1<<<(NN * 32 + 255) / 256, 256>>>(x, W1, a_src1, a_dst1);
    kedge1<<<(NN * 32 + 255) / 256, 256>>>(b1);
    kbn<<<(NN + 255) / 256, 256>>>();
    k4<<<1, 32>>>(gamma1, beta1);
    k5<<<(NN + 255) / 256, 256>>>(W2, a_src2, a_dst2);
    kedge2<<<(NN * 32 + 255) / 256, 256>>>((float*)d_out, b2);
}